// round 15
// baseline (speedup 1.0000x reference)
#include <cuda_runtime.h>
#include <cuda_fp16.h>

#define Bq 512
#define Tq 256
#define Fq 128
#define Hq 256
#define BTF (Bq*Tq*Fq)
#define KSPLIT 112   // B streams Wih-mask k in [0,112); A takes [112,128)

typedef unsigned long long ull;

// ---------------- device scratch (no allocations allowed) ----------------
__device__ __align__(16) float  g_WdhT[Fq*Hq];        // [k in F][j in H]  fp32 (L2)
__device__ __align__(16) __half g_WhT_h[Hq*Fq];       // [k in H][j in F]  fp16 (smem src)
__device__ __align__(16) __half g_WfT_h[Fq*Fq];       // diag zeroed       fp16 (smem src)
__device__ __align__(16) __half g_WcT_h[2*Fq*Fq];     // [k in 2F][j in F] fp16 (smem src)
__device__ __align__(16) __half g_WihT_h[2*Fq*4*Hq];  // [k in 2F][j in 4H] fp16
__device__ __align__(16) __half g_WhhT_h[Hq*4*Hq];    // [k in H][j in 4H]  fp16
__device__ float g_wdx[Fq];
__device__ float g_bsum[4*Hq];
__device__ float g_D[Tq];

// ---------------- packed f32x2 helpers ----------------
__device__ __forceinline__ ull pack2(float x, float y) {
    ull r; asm("mov.b64 %0, {%1,%2};" : "=l"(r) : "f"(x), "f"(y)); return r;
}
__device__ __forceinline__ void unpack2(ull v, float& x, float& y) {
    asm("mov.b64 {%0,%1}, %2;" : "=f"(x), "=f"(y) : "l"(v));
}
__device__ __forceinline__ ull ffma2(ull a, ull b, ull c) {
    ull d; asm("fma.rn.f32x2 %0, %1, %2, %3;" : "=l"(d) : "l"(a), "l"(b), "l"(c)); return d;
}
__device__ __forceinline__ float sigm(float x) {
    return fmaf(0.5f, __tanhf(x * 0.5f), 0.5f);
}

struct __align__(8) H4 { __half2 a, b; };

// ---------------- prep: transpose weights, diag, bias sum, zero scalars ----------------
__global__ void prep_weights(const float* __restrict__ Wdh, const float* __restrict__ Wh,
                             const float* __restrict__ Wf,  const float* __restrict__ Wc,
                             const float* __restrict__ Wih, const float* __restrict__ Whh,
                             const float* __restrict__ Wdx, const float* __restrict__ bih,
                             const float* __restrict__ bhh, float* __restrict__ out, int out_size)
{
    int i0 = blockIdx.x * blockDim.x + threadIdx.x;
    int stride = gridDim.x * blockDim.x;

    for (int idx = i0; idx < 1024*256; idx += stride) {
        int j = idx >> 8, k = idx & 255;
        g_WihT_h[k*1024 + j] = __float2half(Wih[idx]);
        g_WhhT_h[k*1024 + j] = __float2half(Whh[idx]);
    }
    for (int idx = i0; idx < 256*128; idx += stride) {
        int j = idx >> 7, k = idx & 127;
        g_WdhT[k*256 + j] = Wdh[idx];
    }
    for (int idx = i0; idx < 128*256; idx += stride) {
        int j = idx >> 8, k = idx & 255;
        g_WhT_h[k*128 + j] = __float2half(Wh[idx]);
        g_WcT_h[k*128 + j] = __float2half(Wc[idx]);
    }
    for (int idx = i0; idx < 128*128; idx += stride) {
        int j = idx >> 7, k = idx & 127;
        g_WfT_h[k*128 + j] = (j == k) ? __float2half(0.f) : __float2half(Wf[idx]);
    }
    for (int idx = i0; idx < 128; idx += stride)  g_wdx[idx]  = Wdx[idx*128 + idx];
    for (int idx = i0; idx < 1024; idx += stride) g_bsum[idx] = bih[idx] + bhh[idx];
    for (int idx = i0; idx < 2; idx += stride)
        if (BTF + idx < out_size) out[BTF + idx] = 0.f;
}

// ---------------- per-timestep mask denominator ----------------
__global__ void mask_denom(const float* __restrict__ mask)
{
    int t = blockIdx.x;
    float s = 0.f;
    for (int i = threadIdx.x; i < Bq*Fq; i += blockDim.x) {
        int b = i >> 7, f = i & 127;
        s += mask[b*(Tq*Fq) + t*Fq + f];
    }
    for (int o = 16; o; o >>= 1) s += __shfl_down_sync(0xffffffffu, s, o);
    __shared__ float red[8];
    int lane = threadIdx.x & 31, wid = threadIdx.x >> 5;
    if (lane == 0) red[wid] = s;
    __syncthreads();
    if (threadIdx.x == 0) {
        float tt = 0.f;
        #pragma unroll
        for (int w = 0; w < 8; w++) tt += red[w];
        g_D[t] = tt;
    }
}

// fp16-weight GEMV accumulator: act [4][STR] float smem, wbase -> column-quad j0
// of a [*][1024] fp16 transposed matrix. float4 act loads, register packs,
// unroll 8 for L2 latency cover.
template<int LEN, int STR>
__device__ __forceinline__ void gemv_acc_h(const __half* __restrict__ wbase,
                                           const float* __restrict__ act,
                                           ull a01[4], ull a23[4])
{
    #pragma unroll 8
    for (int k4 = 0; k4 < LEN; k4 += 4) {
        float4 iv[4];
        #pragma unroll
        for (int b = 0; b < 4; b++)
            iv[b] = *(const float4*)(act + b*STR + k4);
        #pragma unroll
        for (int kk = 0; kk < 4; kk++) {
            H4 w = *(const H4*)(wbase + (k4 + kk)*1024);
            float2 w01 = __half22float2(w.a);
            float2 w23 = __half22float2(w.b);
            ull w01p = pack2(w01.x, w01.y);
            ull w23p = pack2(w23.x, w23.y);
            #pragma unroll
            for (int b = 0; b < 4; b++) {
                float v = ((const float*)&iv[b])[kk];
                ull vp = pack2(v, v);
                a01[b] = ffma2(w01p, vp, a01[b]);
                a23[b] = ffma2(w23p, vp, a23[b]);
            }
        }
    }
}

// fp16 smem weight GEMV, f-pair outputs, scalar float activations.
__device__ __forceinline__ ull gemv_pair_h(const __half* __restrict__ w, int p,
                                           const float* __restrict__ act, int len)
{
    ull a = 0ull;
    #pragma unroll 8
    for (int k = 0; k < len; k++) {
        float2 wf = __half22float2(((const __half2*)(w + k*Fq))[p]);
        float v = act[k];
        a = ffma2(pack2(wf.x, wf.y), pack2(v, v), a);
    }
    return a;
}

#define DYN_SMEM_BYTES ((Hq*Fq + Fq*Fq + 2*Fq*Fq) * 2)   // 64KB + 32KB + 64KB = 160KB

// ---------------- main persistent kernel: 128 blocks x 512 threads x 4 rows ----------------
__global__ __launch_bounds__(512, 1)
void rits_persistent(const float* __restrict__ values, const float* __restrict__ mask,
                     const float* __restrict__ deltas,
                     const float* __restrict__ bdh, const float* __restrict__ bdx,
                     const float* __restrict__ bh,  const float* __restrict__ bf_,
                     const float* __restrict__ bc,  float* __restrict__ out, int out_size)
{
    // dynamic smem: fp16 Wh (64KB) + Wf (32KB) + Wc (64KB)
    extern __shared__ __align__(16) unsigned char dynsmem[];
    __half* s_WhT = (__half*)dynsmem;                          // [Hq][Fq]
    __half* s_WfT = (__half*)(dynsmem + Hq*Fq*2);              // [Fq][Fq]
    __half* s_WcT = (__half*)(dynsmem + Hq*Fq*2 + Fq*Fq*2);    // [2Fq][Fq]

    __shared__ __align__(16) float sh[4][Hq], sc[4][Hq];
    __shared__ __align__(16) float sx[4][Fq], smk[4][Fq], sd[4][Fq];
    __shared__ __align__(16) float sgx[4][Fq], sxc[4][Fq];
    __shared__ __align__(16) float sgate[4][4*Hq];             // A: cc + mask-chunk + bias
    __shared__ __align__(16) float sgate2[4][4*Hq];            // B: mask[0,112) + Whh
    __shared__ float redx[16], redm[16];

    float (*scc)[Fq] = sxc;   // alias: sxc dead after stage 4, scc written in stage 5

    const int tid = threadIdx.x;
    const int lane = tid & 31, wid = tid >> 5;
    const int rowBase = blockIdx.x * 4;
    const int bq = tid >> 7, fq = tid & 127;       // stage-1 element ownership
    const int jq = tid & 255, j0 = jq * 4;         // gemv column-quad ownership

    // hoisted per-thread invariants
    const float wdx_f = g_wdx[fq], bdx_f = bdx[fq];
    const float bdh_j = bdh[jq];
    const int pA = tid & 63, bA = (tid >> 6) & 3, f0A = 2*pA;
    const float2 bh2 = *(const float2*)&bh[f0A];
    const float2 bf2 = *(const float2*)&bf_[f0A];
    const float2 bc2 = *(const float2*)&bc[f0A];
    const float4 bsum4 = *(const float4*)&g_bsum[j0];

    // one-time smem weight fill (amortized over 256 steps): 160KB as uint4
    {
        const uint4* src = (const uint4*)g_WhT_h;
        uint4* dst = (uint4*)dynsmem;
        for (int i = tid; i < (Hq*Fq*2)/16; i += 512) dst[i] = src[i];
        const uint4* srcf = (const uint4*)g_WfT_h;
        uint4* dstf = (uint4*)(dynsmem + Hq*Fq*2);
        for (int i = tid; i < (Fq*Fq*2)/16; i += 512) dstf[i] = srcf[i];
        const uint4* srcc = (const uint4*)g_WcT_h;
        uint4* dstc = (uint4*)(dynsmem + Hq*Fq*2 + Fq*Fq*2);
        for (int i = tid; i < (2*Fq*Fq*2)/16; i += 512) dstc[i] = srcc[i];
    }
    for (int i = tid; i < 4*Hq; i += 512) { (&sh[0][0])[i] = 0.f; (&sc[0][0])[i] = 0.f; }

    // prologue: stage 1 for t = 0
    {
        int base0 = (rowBase + bq)*(Tq*Fq) + fq;
        float xv = values[base0], mv = mask[base0], dv = deltas[base0];
        sx[bq][fq] = xv; smk[bq][fq] = mv; sd[bq][fq] = dv;
        sgx[bq][fq] = __expf(-fmaxf(dv * wdx_f + bdx_f, 0.f));
    }
    __syncthreads();

    float lx = 0.f, lm = 0.f;    // per-thread loss accumulators (A threads)

    for (int t = 0; t < Tq; t++) {
        // prefetch next-step inputs (registers; consumed at the bottom of the step)
        int tn = (t + 1 < Tq) ? t + 1 : t;
        int basen = (rowBase + bq)*(Tq*Fq) + tn*Fq + fq;
        float xv_n = values[basen], mv_n = mask[basen], dv_n = deltas[basen];

        ull a01[4], a23[4];
        #pragma unroll
        for (int b = 0; b < 4; b++) { a01[b] = 0ull; a23[b] = 0ull; }

        float al0, al1;   // A: alpha pre-activations, computed in W1, used in W2

        // ---- window 1 ----
        // B: Wih-mask k in [0,112).  A: stage 2 + stage-5 Wc gemvs + mask chunk [112,128).
        if (tid >= 256) {
            gemv_acc_h<KSPLIT, Fq>(&g_WihT_h[Fq*1024 + j0], &smk[0][0], a01, a23);
        } else {
            // stage 2: gamma_h, decay h (thread owns j = tid for all 4 rows)
            float a0 = 0.f, a1 = 0.f, a2 = 0.f, a3 = 0.f;
            #pragma unroll 8
            for (int k = 0; k < Fq; k++) {
                float w = g_WdhT[k*Hq + tid];
                a0 += w * sd[0][k]; a1 += w * sd[1][k];
                a2 += w * sd[2][k]; a3 += w * sd[3][k];
            }
            sh[0][tid] *= __expf(-fmaxf(a0 + bdh_j, 0.f));
            sh[1][tid] *= __expf(-fmaxf(a1 + bdh_j, 0.f));
            sh[2][tid] *= __expf(-fmaxf(a2 + bdh_j, 0.f));
            sh[3][tid] *= __expf(-fmaxf(a3 + bdh_j, 0.f));

            // stage-5 alpha gemvs: depend only on gamma_x and mask (ready since stage 1)
            {
                ull a  = gemv_pair_h(s_WcT, pA, &sgx[bA][0], Fq);
                ull a2q = gemv_pair_h(s_WcT + Fq*Fq, pA, &smk[bA][0], Fq);
                float s0, s1, q0, q1;
                unpack2(a, s0, s1); unpack2(a2q, q0, q1);
                al0 = s0 + q0 + bc2.x; al1 = s1 + q1 + bc2.y;
            }

            // A's share of the Wih-mask gemv: k in [112,128)
            gemv_acc_h<Fq - KSPLIT, Fq>(&g_WihT_h[(Fq + KSPLIT)*1024 + j0],
                                        &smk[0][KSPLIT], a01, a23);
        }
        __syncthreads();   // h now final until stage 7

        // ---- window 2 ----
        // B: Whh @ h -> sgate2.  A: stage 3 -> stage 4+combine -> Wih@c_c tail -> sgate.
        if (tid >= 256) {
            gemv_acc_h<Hq, Hq>(&g_WhhT_h[j0], &sh[0][0], a01, a23);
            #pragma unroll
            for (int b2 = 0; b2 < 4; b2++) {
                float g0, g1, g2, g3;
                unpack2(a01[b2], g0, g1);
                unpack2(a23[b2], g2, g3);
                float4 gv; gv.x = g0; gv.y = g1; gv.z = g2; gv.w = g3;
                *(float4*)&sgate2[b2][j0] = gv;
            }
        } else {
            const int p = pA, b = bA, f0 = f0A;
            float2 xp = *(const float2*)&sx[b][f0];
            float2 mp = *(const float2*)&smk[b][f0];

            // ---- stage 3: x_h = Wh @ h + bh; x_c; loss1 (fp16 SMEM) ----
            float xh0, xh1, l1;
            {
                ull a = gemv_pair_h(s_WhT, p, &sh[b][0], Hq);
                float s0, s1; unpack2(a, s0, s1);
                xh0 = s0 + bh2.x; xh1 = s1 + bh2.y;
                float2 xc;
                xc.x = mp.x*xp.x + (1.f - mp.x)*xh0;
                xc.y = mp.y*xp.y + (1.f - mp.y)*xh1;
                *(float2*)&sxc[b][f0] = xc;
                l1 = fabsf(xh0 - xp.x)*mp.x + fabsf(xh1 - xp.y)*mp.y;
            }
            asm volatile("bar.sync 1, 256;" ::: "memory");

            // ---- stage 4 + combine: z_h, then c_h/c_c with alpha from W1 ----
            {
                ull a = gemv_pair_h(s_WfT, p, &sxc[b][0], Fq);
                float s0, s1; unpack2(a, s0, s1);
                float zh0 = s0 + bf2.x, zh1 = s1 + bf2.y;
                float l2 = fabsf(zh0 - xp.x)*mp.x + fabsf(zh1 - xp.y)*mp.y;

                float ch0 = al0*zh0 + (1.f - al0)*xh0;
                float ch1 = al1*zh1 + (1.f - al1)*xh1;
                float l3 = fabsf(ch0 - xp.x)*mp.x + fabsf(ch1 - xp.y)*mp.y;
                float2 cc;
                cc.x = mp.x*xp.x + (1.f - mp.x)*ch0;
                cc.y = mp.y*xp.y + (1.f - mp.y)*ch1;
                *(float2*)&scc[b][f0] = cc;
                *(float2*)&out[(rowBase + b)*(Tq*Fq) + t*Fq + f0] = cc;
                float inv = __fdividef(1.f, g_D[t] + 1e-9f);
                lx += (l1 + l2 + (float)(Tq - t)*l3) * inv;
                lm += l3 * inv;
            }
            asm volatile("bar.sync 1, 256;" ::: "memory");

            // ---- A tail: Wih @ c_c; sgate = cc-part + mask-chunk + (bih + bhh) ----
            gemv_acc_h<Fq, Fq>(&g_WihT_h[j0], &scc[0][0], a01, a23);
            #pragma unroll
            for (int b2 = 0; b2 < 4; b2++) {
                float g0, g1, g2, g3;
                unpack2(a01[b2], g0, g1);
                unpack2(a23[b2], g2, g3);
                float4 gv;
                gv.x = g0 + bsum4.x; gv.y = g1 + bsum4.y;
                gv.z = g2 + bsum4.z; gv.w = g3 + bsum4.w;
                *(float4*)&sgate[b2][j0] = gv;
            }
        }
        __syncthreads();

        // ---- phase E: stage 1(t+1) from prefetch + stage 7 (LSTM), one barrier ----
        {
            sx[bq][fq] = xv_n; smk[bq][fq] = mv_n; sd[bq][fq] = dv_n;
            sgx[bq][fq] = __expf(-fmaxf(dv_n * wdx_f + bdx_f, 0.f));

            int u = tid & 255;
            int bp = (tid >> 8) * 2;
            #pragma unroll
            for (int bb = 0; bb < 2; bb++) {
                int b = bp + bb;
                float ig = sgate[b][u]        + sgate2[b][u];
                float fg = sgate[b][Hq + u]   + sgate2[b][Hq + u];
                float gg = sgate[b][2*Hq + u] + sgate2[b][2*Hq + u];
                float og = sgate[b][3*Hq + u] + sgate2[b][3*Hq + u];
                float si = sigm(ig);
                float sf = sigm(fg);
                float so = sigm(og);
                float tg = __tanhf(gg);
                float cn = sf*sc[b][u] + si*tg;
                sc[b][u] = cn;
                sh[b][u] = so * __tanhf(cn);
            }
        }
        __syncthreads();
    }

    // ---- final loss reduction across the block ----
    for (int o = 16; o; o >>= 1) {
        lx += __shfl_down_sync(0xffffffffu, lx, o);
        lm += __shfl_down_sync(0xffffffffu, lm, o);
    }
    if (lane == 0) { redx[wid] = lx; redm[wid] = lm; }
    __syncthreads();
    if (tid == 0 && BTF + 1 < out_size) {
        float tx = 0.f, tm = 0.f;
        #pragma unroll
        for (int w = 0; w < 16; w++) { tx += redx[w]; tm += redm[w]; }
        atomicAdd(&out[BTF],     tx * (1.f / (Tq * 3.0f)));
        atomicAdd(&out[BTF + 1], tm * (1.f / (float)Tq));
    }
}

// ---------------- launch ----------------
extern "C" void kernel_launch(void* const* d_in, const int* in_sizes, int n_in,
                              void* d_out, int out_size)
{
    const float* values = (const float*)d_in[0];
    const float* mask   = (const float*)d_in[1];
    const float* deltas = (const float*)d_in[2];
    const float* Wdh    = (const float*)d_in[3];
    const float* bdh    = (const float*)d_in[4];
    const float* Wdx    = (const float*)d_in[5];
    const float* bdx    = (const float*)d_in[6];
    const float* Wh     = (const float*)d_in[7];
    const float* bh     = (const float*)d_in[8];
    const float* Wf     = (const float*)d_in[9];
    const float* bf_    = (const float*)d_in[10];
    const float* Wc     = (const float*)d_in[11];
    const float* bc     = (const float*)d_in[12];
    const float* Wih    = (const float*)d_in[13];
    const float* Whh    = (const float*)d_in[14];
    const float* bih    = (const float*)d_in[15];
    const float* bhh    = (const float*)d_in[16];
    float* out = (float*)d_out;

    cudaFuncSetAttribute(rits_persistent,
                         cudaFuncAttributeMaxDynamicSharedMemorySize, DYN_SMEM_BYTES);

    prep_weights<<<256, 256>>>(Wdh, Wh, Wf, Wc, Wih, Whh, Wdx, bih, bhh, out, out_size);
    mask_denom<<<Tq, 256>>>(mask);
    rits_persistent<<<Bq/4, 512, DYN_SMEM_BYTES>>>(values, mask, deltas, bdh, bdx,
                                                   bh, bf_, bc, out, out_size);
}

// round 16
// speedup vs baseline: 1.0236x; 1.0236x over previous
#include <cuda_runtime.h>
#include <cuda_fp16.h>

#define Bq 512
#define Tq 256
#define Fq 128
#define Hq 256
#define BTF (Bq*Tq*Fq)

typedef unsigned long long ull;

// ---------------- device scratch (no allocations allowed) ----------------
__device__ __align__(16) float  g_WdhT[Fq*Hq];        // [k in F][j in H]  fp32 (L2)
__device__ __align__(16) __half g_WhT_h[Hq*Fq];       // [k in H][j in F]  fp16 (smem src)
__device__ __align__(16) __half g_WfT_h[Fq*Fq];       // diag zeroed       fp16 (smem src)
__device__ __align__(16) __half g_WcT_h[2*Fq*Fq];     // [k in 2F][j in F] fp16 (smem src)
__device__ __align__(16) __half g_WihT_h[2*Fq*4*Hq];  // [k in 2F][j in 4H] fp16
__device__ __align__(16) __half g_WhhT_h[Hq*4*Hq];    // [k in H][j in 4H]  fp16
__device__ float g_wdx[Fq];
__device__ float g_bsum[4*Hq];
__device__ float g_D[Tq];

// ---------------- packed f32x2 helpers ----------------
__device__ __forceinline__ ull pack2(float x, float y) {
    ull r; asm("mov.b64 %0, {%1,%2};" : "=l"(r) : "f"(x), "f"(y)); return r;
}
__device__ __forceinline__ void unpack2(ull v, float& x, float& y) {
    asm("mov.b64 {%0,%1}, %2;" : "=f"(x), "=f"(y) : "l"(v));
}
__device__ __forceinline__ ull ffma2(ull a, ull b, ull c) {
    ull d; asm("fma.rn.f32x2 %0, %1, %2, %3;" : "=l"(d) : "l"(a), "l"(b), "l"(c)); return d;
}
__device__ __forceinline__ float sigm(float x) {
    return fmaf(0.5f, __tanhf(x * 0.5f), 0.5f);
}

struct __align__(8) H4 { __half2 a, b; };

// ---------------- prep: transpose weights, diag, bias sum, zero scalars ----------------
__global__ void prep_weights(const float* __restrict__ Wdh, const float* __restrict__ Wh,
                             const float* __restrict__ Wf,  const float* __restrict__ Wc,
                             const float* __restrict__ Wih, const float* __restrict__ Whh,
                             const float* __restrict__ Wdx, const float* __restrict__ bih,
                             const float* __restrict__ bhh, float* __restrict__ out, int out_size)
{
    int i0 = blockIdx.x * blockDim.x + threadIdx.x;
    int stride = gridDim.x * blockDim.x;

    for (int idx = i0; idx < 1024*256; idx += stride) {
        int j = idx >> 8, k = idx & 255;
        g_WihT_h[k*1024 + j] = __float2half(Wih[idx]);
        g_WhhT_h[k*1024 + j] = __float2half(Whh[idx]);
    }
    for (int idx = i0; idx < 256*128; idx += stride) {
        int j = idx >> 7, k = idx & 127;
        g_WdhT[k*256 + j] = Wdh[idx];
    }
    for (int idx = i0; idx < 128*256; idx += stride) {
        int j = idx >> 8, k = idx & 255;
        g_WhT_h[k*128 + j] = __float2half(Wh[idx]);
        g_WcT_h[k*128 + j] = __float2half(Wc[idx]);
    }
    for (int idx = i0; idx < 128*128; idx += stride) {
        int j = idx >> 7, k = idx & 127;
        g_WfT_h[k*128 + j] = (j == k) ? __float2half(0.f) : __float2half(Wf[idx]);
    }
    for (int idx = i0; idx < 128; idx += stride)  g_wdx[idx]  = Wdx[idx*128 + idx];
    for (int idx = i0; idx < 1024; idx += stride) g_bsum[idx] = bih[idx] + bhh[idx];
    for (int idx = i0; idx < 2; idx += stride)
        if (BTF + idx < out_size) out[BTF + idx] = 0.f;
}

// ---------------- per-timestep mask denominator ----------------
__global__ void mask_denom(const float* __restrict__ mask)
{
    int t = blockIdx.x;
    float s = 0.f;
    for (int i = threadIdx.x; i < Bq*Fq; i += blockDim.x) {
        int b = i >> 7, f = i & 127;
        s += mask[b*(Tq*Fq) + t*Fq + f];
    }
    for (int o = 16; o; o >>= 1) s += __shfl_down_sync(0xffffffffu, s, o);
    __shared__ float red[8];
    int lane = threadIdx.x & 31, wid = threadIdx.x >> 5;
    if (lane == 0) red[wid] = s;
    __syncthreads();
    if (threadIdx.x == 0) {
        float tt = 0.f;
        #pragma unroll
        for (int w = 0; w < 8; w++) tt += red[w];
        g_D[t] = tt;
    }
}

// fp16-weight GEMV accumulator: act [4][STR] float smem, wbase -> column-quad j0
// of a [*][1024] fp16 transposed matrix. float4 act loads, register packs,
// unroll 8 for L2 latency cover.
template<int LEN, int STR>
__device__ __forceinline__ void gemv_acc_h(const __half* __restrict__ wbase,
                                           const float* __restrict__ act,
                                           ull a01[4], ull a23[4])
{
    #pragma unroll 8
    for (int k4 = 0; k4 < LEN; k4 += 4) {
        float4 iv[4];
        #pragma unroll
        for (int b = 0; b < 4; b++)
            iv[b] = *(const float4*)(act + b*STR + k4);
        #pragma unroll
        for (int kk = 0; kk < 4; kk++) {
            H4 w = *(const H4*)(wbase + (k4 + kk)*1024);
            float2 w01 = __half22float2(w.a);
            float2 w23 = __half22float2(w.b);
            ull w01p = pack2(w01.x, w01.y);
            ull w23p = pack2(w23.x, w23.y);
            #pragma unroll
            for (int b = 0; b < 4; b++) {
                float v = ((const float*)&iv[b])[kk];
                ull vp = pack2(v, v);
                a01[b] = ffma2(w01p, vp, a01[b]);
                a23[b] = ffma2(w23p, vp, a23[b]);
            }
        }
    }
}

// fp16 smem weight GEMV, f-pair outputs, scalar float activations.
__device__ __forceinline__ ull gemv_pair_h(const __half* __restrict__ w, int p,
                                           const float* __restrict__ act, int len)
{
    ull a = 0ull;
    #pragma unroll 8
    for (int k = 0; k < len; k++) {
        float2 wf = __half22float2(((const __half2*)(w + k*Fq))[p]);
        float v = act[k];
        a = ffma2(pack2(wf.x, wf.y), pack2(v, v), a);
    }
    return a;
}

#define DYN_SMEM_BYTES ((Hq*Fq + Fq*Fq + 2*Fq*Fq) * 2)   // 64KB + 32KB + 64KB = 160KB

// ---------------- main persistent kernel: 128 blocks x 512 threads x 4 rows ----------------
__global__ __launch_bounds__(512, 1)
void rits_persistent(const float* __restrict__ values, const float* __restrict__ mask,
                     const float* __restrict__ deltas,
                     const float* __restrict__ bdh, const float* __restrict__ bdx,
                     const float* __restrict__ bh,  const float* __restrict__ bf_,
                     const float* __restrict__ bc,  float* __restrict__ out, int out_size)
{
    // dynamic smem: fp16 Wh (64KB) + Wf (32KB) + Wc (64KB)
    extern __shared__ __align__(16) unsigned char dynsmem[];
    __half* s_WhT = (__half*)dynsmem;                          // [Hq][Fq]
    __half* s_WfT = (__half*)(dynsmem + Hq*Fq*2);              // [Fq][Fq]
    __half* s_WcT = (__half*)(dynsmem + Hq*Fq*2 + Fq*Fq*2);    // [2Fq][Fq]

    __shared__ __align__(16) float sh[4][Hq], sc[4][Hq];
    __shared__ __align__(16) float sx[4][Fq], smk[4][Fq], sd[4][Fq];
    __shared__ __align__(16) float sgx[4][Fq], sxc[4][Fq];
    __shared__ __align__(16) float sccb[4][Fq];                // SEPARATE c_c buffer (no alias!)
    __shared__ __align__(16) float sgate[4][4*Hq];             // A: cc + bias
    __shared__ __align__(16) float sgate2[4][4*Hq];            // B: mask + Whh
    __shared__ float redx[16], redm[16];

    const int tid = threadIdx.x;
    const int lane = tid & 31, wid = tid >> 5;
    const int rowBase = blockIdx.x * 4;
    const int bq = tid >> 7, fq = tid & 127;       // stage-1 element ownership
    const int jq = tid & 255, j0 = jq * 4;         // gemv column-quad ownership

    // hoisted per-thread invariants
    const float wdx_f = g_wdx[fq], bdx_f = bdx[fq];
    const float bdh_j = bdh[jq];
    const int pA = tid & 63, bA = (tid >> 6) & 3, f0A = 2*pA;
    const float2 bh2 = *(const float2*)&bh[f0A];
    const float2 bf2 = *(const float2*)&bf_[f0A];
    const float2 bc2 = *(const float2*)&bc[f0A];
    const float4 bsum4 = *(const float4*)&g_bsum[j0];

    // one-time smem weight fill (amortized over 256 steps): 160KB as uint4
    {
        const uint4* src = (const uint4*)g_WhT_h;
        uint4* dst = (uint4*)dynsmem;
        for (int i = tid; i < (Hq*Fq*2)/16; i += 512) dst[i] = src[i];
        const uint4* srcf = (const uint4*)g_WfT_h;
        uint4* dstf = (uint4*)(dynsmem + Hq*Fq*2);
        for (int i = tid; i < (Fq*Fq*2)/16; i += 512) dstf[i] = srcf[i];
        const uint4* srcc = (const uint4*)g_WcT_h;
        uint4* dstc = (uint4*)(dynsmem + Hq*Fq*2 + Fq*Fq*2);
        for (int i = tid; i < (2*Fq*Fq*2)/16; i += 512) dstc[i] = srcc[i];
    }
    for (int i = tid; i < 4*Hq; i += 512) { (&sh[0][0])[i] = 0.f; (&sc[0][0])[i] = 0.f; }

    // prologue: stage 1 for t = 0
    {
        int base0 = (rowBase + bq)*(Tq*Fq) + fq;
        float xv = values[base0], mv = mask[base0], dv = deltas[base0];
        sx[bq][fq] = xv; smk[bq][fq] = mv; sd[bq][fq] = dv;
        sgx[bq][fq] = __expf(-fmaxf(dv * wdx_f + bdx_f, 0.f));
    }
    __syncthreads();

    float lx = 0.f, lm = 0.f;    // per-thread loss accumulators (A threads)

    for (int t = 0; t < Tq; t++) {
        // prefetch next-step inputs (registers; consumed at the bottom of the step)
        int tn = (t + 1 < Tq) ? t + 1 : t;
        int basen = (rowBase + bq)*(Tq*Fq) + tn*Fq + fq;
        float xv_n = values[basen], mv_n = mask[basen], dv_n = deltas[basen];

        ull a01[4], a23[4];
        #pragma unroll
        for (int b = 0; b < 4; b++) { a01[b] = 0ull; a23[b] = 0ull; }

        float al0, al1;   // A: alpha pre-activations, computed in W1, used in W2

        // ---- window 1 ----
        // B: full Wih-mask gemv.  A: stage 2 (MLP-32 batched) + stage-5 alpha gemvs.
        if (tid >= 256) {
            gemv_acc_h<Fq, Fq>(&g_WihT_h[Fq*1024 + j0], &smk[0][0], a01, a23);
        } else {
            // stage 2: gamma_h, decay h — 4 windows of 32 batched LDGs (MLP=32)
            float a0 = 0.f, a1 = 0.f, a2 = 0.f, a3 = 0.f;
            #pragma unroll
            for (int kk = 0; kk < 4; kk++) {
                float w[32];
                #pragma unroll
                for (int i = 0; i < 32; i++)
                    w[i] = g_WdhT[(kk*32 + i)*Hq + tid];
                #pragma unroll
                for (int i = 0; i < 32; i++) {
                    int k = kk*32 + i;
                    a0 += w[i] * sd[0][k]; a1 += w[i] * sd[1][k];
                    a2 += w[i] * sd[2][k]; a3 += w[i] * sd[3][k];
                }
            }
            sh[0][tid] *= __expf(-fmaxf(a0 + bdh_j, 0.f));
            sh[1][tid] *= __expf(-fmaxf(a1 + bdh_j, 0.f));
            sh[2][tid] *= __expf(-fmaxf(a2 + bdh_j, 0.f));
            sh[3][tid] *= __expf(-fmaxf(a3 + bdh_j, 0.f));

            // stage-5 alpha gemvs: depend only on gamma_x and mask (ready since stage 1)
            {
                ull a  = gemv_pair_h(s_WcT, pA, &sgx[bA][0], Fq);
                ull a2q = gemv_pair_h(s_WcT + Fq*Fq, pA, &smk[bA][0], Fq);
                float s0, s1, q0, q1;
                unpack2(a, s0, s1); unpack2(a2q, q0, q1);
                al0 = s0 + q0 + bc2.x; al1 = s1 + q1 + bc2.y;
            }
        }
        __syncthreads();   // h now final until stage 7

        // ---- window 2 ----
        // B: Whh @ h -> sgate2.  A: stage 3 -> stage 4+combine -> Wih@c_c tail -> sgate.
        if (tid >= 256) {
            gemv_acc_h<Hq, Hq>(&g_WhhT_h[j0], &sh[0][0], a01, a23);
            #pragma unroll
            for (int b2 = 0; b2 < 4; b2++) {
                float g0, g1, g2, g3;
                unpack2(a01[b2], g0, g1);
                unpack2(a23[b2], g2, g3);
                float4 gv; gv.x = g0; gv.y = g1; gv.z = g2; gv.w = g3;
                *(float4*)&sgate2[b2][j0] = gv;
            }
        } else {
            const int p = pA, b = bA, f0 = f0A;
            float2 xp = *(const float2*)&sx[b][f0];
            float2 mp = *(const float2*)&smk[b][f0];

            // ---- stage 3: x_h = Wh @ h + bh; x_c; loss1 (fp16 SMEM) ----
            float xh0, xh1, l1;
            {
                ull a = gemv_pair_h(s_WhT, p, &sh[b][0], Hq);
                float s0, s1; unpack2(a, s0, s1);
                xh0 = s0 + bh2.x; xh1 = s1 + bh2.y;
                float2 xc;
                xc.x = mp.x*xp.x + (1.f - mp.x)*xh0;
                xc.y = mp.y*xp.y + (1.f - mp.y)*xh1;
                *(float2*)&sxc[b][f0] = xc;
                l1 = fabsf(xh0 - xp.x)*mp.x + fabsf(xh1 - xp.y)*mp.y;
            }
            asm volatile("bar.sync 1, 256;" ::: "memory");

            // ---- stage 4 + combine: z_h, then c_h/c_c with alpha from W1 ----
            // (writes go to sccb — separate buffer, so the full-row sxc reads in the
            //  Wf gemv cannot race with any thread's c_c store)
            {
                ull a = gemv_pair_h(s_WfT, p, &sxc[b][0], Fq);
                float s0, s1; unpack2(a, s0, s1);
                float zh0 = s0 + bf2.x, zh1 = s1 + bf2.y;
                float l2 = fabsf(zh0 - xp.x)*mp.x + fabsf(zh1 - xp.y)*mp.y;

                float ch0 = al0*zh0 + (1.f - al0)*xh0;
                float ch1 = al1*zh1 + (1.f - al1)*xh1;
                float l3 = fabsf(ch0 - xp.x)*mp.x + fabsf(ch1 - xp.y)*mp.y;
                float2 cc;
                cc.x = mp.x*xp.x + (1.f - mp.x)*ch0;
                cc.y = mp.y*xp.y + (1.f - mp.y)*ch1;
                *(float2*)&sccb[b][f0] = cc;
                *(float2*)&out[(rowBase + b)*(Tq*Fq) + t*Fq + f0] = cc;
                float inv = __fdividef(1.f, g_D[t] + 1e-9f);
                lx += (l1 + l2 + (float)(Tq - t)*l3) * inv;
                lm += l3 * inv;
            }
            asm volatile("bar.sync 1, 256;" ::: "memory");

            // ---- A tail: Wih @ c_c; sgate = cc-part + (bih + bhh) ----
            gemv_acc_h<Fq, Fq>(&g_WihT_h[j0], &sccb[0][0], a01, a23);
            #pragma unroll
            for (int b2 = 0; b2 < 4; b2++) {
                float g0, g1, g2, g3;
                unpack2(a01[b2], g0, g1);
                unpack2(a23[b2], g2, g3);
                float4 gv;
                gv.x = g0 + bsum4.x; gv.y = g1 + bsum4.y;
                gv.z = g2 + bsum4.z; gv.w = g3 + bsum4.w;
                *(float4*)&sgate[b2][j0] = gv;
            }
        }
        __syncthreads();

        // ---- phase E: stage 1(t+1) from prefetch + stage 7 (LSTM), one barrier ----
        {
            sx[bq][fq] = xv_n; smk[bq][fq] = mv_n; sd[bq][fq] = dv_n;
            sgx[bq][fq] = __expf(-fmaxf(dv_n * wdx_f + bdx_f, 0.f));

            int u = tid & 255;
            int bp = (tid >> 8) * 2;
            #pragma unroll
            for (int bb = 0; bb < 2; bb++) {
                int b = bp + bb;
                float ig = sgate[b][u]        + sgate2[b][u];
                float fg = sgate[b][Hq + u]   + sgate2[b][Hq + u];
                float gg = sgate[b][2*Hq + u] + sgate2[b][2*Hq + u];
                float og = sgate[b][3*Hq + u] + sgate2[b][3*Hq + u];
                float si = sigm(ig);
                float sf = sigm(fg);
                float so = sigm(og);
                float tg = __tanhf(gg);
                float cn = sf*sc[b][u] + si*tg;
                sc[b][u] = cn;
                sh[b][u] = so * __tanhf(cn);
            }
        }
        __syncthreads();
    }

    // ---- final loss reduction across the block ----
    for (int o = 16; o; o >>= 1) {
        lx += __shfl_down_sync(0xffffffffu, lx, o);
        lm += __shfl_down_sync(0xffffffffu, lm, o);
    }
    if (lane == 0) { redx[wid] = lx; redm[wid] = lm; }
    __syncthreads();
    if (tid == 0 && BTF + 1 < out_size) {
        float tx = 0.f, tm = 0.f;
        #pragma unroll
        for (int w = 0; w < 16; w++) { tx += redx[w]; tm += redm[w]; }
        atomicAdd(&out[BTF],     tx * (1.f / (Tq * 3.0f)));
        atomicAdd(&out[BTF + 1], tm * (1.f / (float)Tq));
    }
}

// ---------------- launch ----------------
extern "C" void kernel_launch(void* const* d_in, const int* in_sizes, int n_in,
                              void* d_out, int out_size)
{
    const float* values = (const float*)d_in[0];
    const float* mask   = (const float*)d_in[1];
    const float* deltas = (const float*)d_in[2];
    const float* Wdh    = (const float*)d_in[3];
    const float* bdh    = (const float*)d_in[4];
    const float* Wdx    = (const float*)d_in[5];
    const float* bdx    = (const float*)d_in[6];
    const float* Wh     = (const float*)d_in[7];
    const float* bh     = (const float*)d_in[8];
    const float* Wf     = (const float*)d_in[9];
    const float* bf_    = (const float*)d_in[10];
    const float* Wc     = (const float*)d_in[11];
    const float* bc     = (const float*)d_in[12];
    const float* Wih    = (const float*)d_in[13];
    const float* Whh    = (const float*)d_in[14];
    const float* bih    = (const float*)d_in[15];
    const float* bhh    = (const float*)d_in[16];
    float* out = (float*)d_out;

    cudaFuncSetAttribute(rits_persistent,
                         cudaFuncAttributeMaxDynamicSharedMemorySize, DYN_SMEM_BYTES);

    prep_weights<<<256, 256>>>(Wdh, Wh, Wf, Wc, Wih, Whh, Wdx, bih, bhh, out, out_size);
    mask_denom<<<Tq, 256>>>(mask);
    rits_persistent<<<Bq/4, 512, DYN_SMEM_BYTES>>>(values, mask, deltas, bdh, bdx,
                                                   bh, bf_, bc, out, out_size);
}

// round 17
// speedup vs baseline: 1.0253x; 1.0017x over previous
#include <cuda_runtime.h>
#include <cuda_fp16.h>

#define Bq 512
#define Tq 256
#define Fq 128
#define Hq 256
#define BTF (Bq*Tq*Fq)

typedef unsigned long long ull;

// ---------------- device scratch (no allocations allowed) ----------------
__device__ __align__(16) float  g_WdhT2[Fq*Hq];       // pair-interleaved: [k/2][j][2] fp32
__device__ __align__(16) __half g_WhT_h[Hq*Fq];       // [k in H][j in F]  fp16 (smem src)
__device__ __align__(16) __half g_WfT_h[Fq*Fq];       // diag zeroed       fp16 (smem src)
__device__ __align__(16) __half g_WcT_h[2*Fq*Fq];     // [k in 2F][j in F] fp16 (smem src)
__device__ __align__(16) __half g_WihT_h[2*Fq*4*Hq];  // [k in 2F][j in 4H] fp16
__device__ __align__(16) __half g_WhhT_h[Hq*4*Hq];    // [k in H][j in 4H]  fp16
__device__ float g_wdx[Fq];
__device__ float g_bsum[4*Hq];
__device__ float g_D[Tq];

// ---------------- packed f32x2 helpers ----------------
__device__ __forceinline__ ull pack2(float x, float y) {
    ull r; asm("mov.b64 %0, {%1,%2};" : "=l"(r) : "f"(x), "f"(y)); return r;
}
__device__ __forceinline__ void unpack2(ull v, float& x, float& y) {
    asm("mov.b64 {%0,%1}, %2;" : "=f"(x), "=f"(y) : "l"(v));
}
__device__ __forceinline__ ull ffma2(ull a, ull b, ull c) {
    ull d; asm("fma.rn.f32x2 %0, %1, %2, %3;" : "=l"(d) : "l"(a), "l"(b), "l"(c)); return d;
}
__device__ __forceinline__ ull fadd2(ull a, ull b) {
    ull d; asm("add.rn.f32x2 %0, %1, %2;" : "=l"(d) : "l"(a), "l"(b)); return d;
}
__device__ __forceinline__ float sigm(float x) {
    return fmaf(0.5f, __tanhf(x * 0.5f), 0.5f);
}

struct __align__(8) H4 { __half2 a, b; };

// ---------------- prep: transpose weights, diag, bias sum, zero scalars ----------------
__global__ void prep_weights(const float* __restrict__ Wdh, const float* __restrict__ Wh,
                             const float* __restrict__ Wf,  const float* __restrict__ Wc,
                             const float* __restrict__ Wih, const float* __restrict__ Whh,
                             const float* __restrict__ Wdx, const float* __restrict__ bih,
                             const float* __restrict__ bhh, float* __restrict__ out, int out_size)
{
    int i0 = blockIdx.x * blockDim.x + threadIdx.x;
    int stride = gridDim.x * blockDim.x;

    for (int idx = i0; idx < 1024*256; idx += stride) {
        int j = idx >> 8, k = idx & 255;
        g_WihT_h[k*1024 + j] = __float2half(Wih[idx]);
        g_WhhT_h[k*1024 + j] = __float2half(Whh[idx]);
    }
    // Wdh [256 j, 128 k] -> pair-interleaved [k/2][j][2] fp32:
    // g_WdhT2[(k>>1)*512 + j*2 + (k&1)] = Wdh[j][k]
    for (int idx = i0; idx < 256*128; idx += stride) {
        int j = idx >> 7, k = idx & 127;
        g_WdhT2[(k >> 1)*512 + j*2 + (k & 1)] = Wdh[idx];
    }
    for (int idx = i0; idx < 128*256; idx += stride) {
        int j = idx >> 8, k = idx & 255;
        g_WhT_h[k*128 + j] = __float2half(Wh[idx]);
        g_WcT_h[k*128 + j] = __float2half(Wc[idx]);
    }
    for (int idx = i0; idx < 128*128; idx += stride) {
        int j = idx >> 7, k = idx & 127;
        g_WfT_h[k*128 + j] = (j == k) ? __float2half(0.f) : __float2half(Wf[idx]);
    }
    for (int idx = i0; idx < 128; idx += stride)  g_wdx[idx]  = Wdx[idx*128 + idx];
    for (int idx = i0; idx < 1024; idx += stride) g_bsum[idx] = bih[idx] + bhh[idx];
    for (int idx = i0; idx < 2; idx += stride)
        if (BTF + idx < out_size) out[BTF + idx] = 0.f;
}

// ---------------- per-timestep mask denominator ----------------
__global__ void mask_denom(const float* __restrict__ mask)
{
    int t = blockIdx.x;
    float s = 0.f;
    for (int i = threadIdx.x; i < Bq*Fq; i += blockDim.x) {
        int b = i >> 7, f = i & 127;
        s += mask[b*(Tq*Fq) + t*Fq + f];
    }
    for (int o = 16; o; o >>= 1) s += __shfl_down_sync(0xffffffffu, s, o);
    __shared__ float red[8];
    int lane = threadIdx.x & 31, wid = threadIdx.x >> 5;
    if (lane == 0) red[wid] = s;
    __syncthreads();
    if (threadIdx.x == 0) {
        float tt = 0.f;
        #pragma unroll
        for (int w = 0; w < 8; w++) tt += red[w];
        g_D[t] = tt;
    }
}

// fp16-weight GEMV accumulator: act [4][STR] float smem, wbase -> column-quad j0
// of a [*][1024] fp16 transposed matrix. float4 act loads, register packs,
// unroll 8 for L2 latency cover.
template<int LEN, int STR>
__device__ __forceinline__ void gemv_acc_h(const __half* __restrict__ wbase,
                                           const float* __restrict__ act,
                                           ull a01[4], ull a23[4])
{
    #pragma unroll 8
    for (int k4 = 0; k4 < LEN; k4 += 4) {
        float4 iv[4];
        #pragma unroll
        for (int b = 0; b < 4; b++)
            iv[b] = *(const float4*)(act + b*STR + k4);
        #pragma unroll
        for (int kk = 0; kk < 4; kk++) {
            H4 w = *(const H4*)(wbase + (k4 + kk)*1024);
            float2 w01 = __half22float2(w.a);
            float2 w23 = __half22float2(w.b);
            ull w01p = pack2(w01.x, w01.y);
            ull w23p = pack2(w23.x, w23.y);
            #pragma unroll
            for (int b = 0; b < 4; b++) {
                float v = ((const float*)&iv[b])[kk];
                ull vp = pack2(v, v);
                a01[b] = ffma2(w01p, vp, a01[b]);
                a23[b] = ffma2(w23p, vp, a23[b]);
            }
        }
    }
}

// fp16 smem weight GEMV, f-pair outputs, scalar float activations.
// Dual accumulator chains (even/odd k) to halve the ffma2 dependency depth.
__device__ __forceinline__ ull gemv_pair_h(const __half* __restrict__ w, int p,
                                           const float* __restrict__ act, int len)
{
    ull a0 = 0ull, a1 = 0ull;
    #pragma unroll 8
    for (int k = 0; k < len; k += 2) {
        float2 wf0 = __half22float2(((const __half2*)(w + k*Fq))[p]);
        float v0 = act[k];
        a0 = ffma2(pack2(wf0.x, wf0.y), pack2(v0, v0), a0);
        float2 wf1 = __half22float2(((const __half2*)(w + (k+1)*Fq))[p]);
        float v1 = act[k+1];
        a1 = ffma2(pack2(wf1.x, wf1.y), pack2(v1, v1), a1);
    }
    return fadd2(a0, a1);
}

#define DYN_SMEM_BYTES ((Hq*Fq + Fq*Fq + 2*Fq*Fq) * 2)   // 64KB + 32KB + 64KB = 160KB

// ---------------- main persistent kernel: 128 blocks x 512 threads x 4 rows ----------------
__global__ __launch_bounds__(512, 1)
void rits_persistent(const float* __restrict__ values, const float* __restrict__ mask,
                     const float* __restrict__ deltas,
                     const float* __restrict__ bdh, const float* __restrict__ bdx,
                     const float* __restrict__ bh,  const float* __restrict__ bf_,
                     const float* __restrict__ bc,  float* __restrict__ out, int out_size)
{
    // dynamic smem: fp16 Wh (64KB) + Wf (32KB) + Wc (64KB)
    extern __shared__ __align__(16) unsigned char dynsmem[];
    __half* s_WhT = (__half*)dynsmem;                          // [Hq][Fq]
    __half* s_WfT = (__half*)(dynsmem + Hq*Fq*2);              // [Fq][Fq]
    __half* s_WcT = (__half*)(dynsmem + Hq*Fq*2 + Fq*Fq*2);    // [2Fq][Fq]

    __shared__ __align__(16) float sh[4][Hq], sc[4][Hq];
    __shared__ __align__(16) float sx[4][Fq], smk[4][Fq], sd[4][Fq];
    __shared__ __align__(16) float sgx[4][Fq], sxc[4][Fq];
    __shared__ __align__(16) float sccb[4][Fq];                // separate c_c buffer
    __shared__ __align__(16) float sgate[4][4*Hq];             // A: cc + bias
    __shared__ __align__(16) float sgate2[4][4*Hq];            // B: mask + Whh
    __shared__ float redx[16], redm[16];

    const int tid = threadIdx.x;
    const int lane = tid & 31, wid = tid >> 5;
    const int rowBase = blockIdx.x * 4;
    const int bq = tid >> 7, fq = tid & 127;       // stage-1 element ownership
    const int jq = tid & 255, j0 = jq * 4;         // gemv column-quad ownership

    // hoisted per-thread invariants
    const float wdx_f = g_wdx[fq], bdx_f = bdx[fq];
    const float bdh_j = bdh[jq];
    const int pA = tid & 63, bA = (tid >> 6) & 3, f0A = 2*pA;
    const float2 bh2 = *(const float2*)&bh[f0A];
    const float2 bf2 = *(const float2*)&bf_[f0A];
    const float2 bc2 = *(const float2*)&bc[f0A];
    const float4 bsum4 = *(const float4*)&g_bsum[j0];

    // one-time smem weight fill (amortized over 256 steps): 160KB as uint4
    {
        const uint4* src = (const uint4*)g_WhT_h;
        uint4* dst = (uint4*)dynsmem;
        for (int i = tid; i < (Hq*Fq*2)/16; i += 512) dst[i] = src[i];
        const uint4* srcf = (const uint4*)g_WfT_h;
        uint4* dstf = (uint4*)(dynsmem + Hq*Fq*2);
        for (int i = tid; i < (Fq*Fq*2)/16; i += 512) dstf[i] = srcf[i];
        const uint4* srcc = (const uint4*)g_WcT_h;
        uint4* dstc = (uint4*)(dynsmem + Hq*Fq*2 + Fq*Fq*2);
        for (int i = tid; i < (2*Fq*Fq*2)/16; i += 512) dstc[i] = srcc[i];
    }
    for (int i = tid; i < 4*Hq; i += 512) { (&sh[0][0])[i] = 0.f; (&sc[0][0])[i] = 0.f; }

    // prologue: stage 1 for t = 0
    {
        int base0 = (rowBase + bq)*(Tq*Fq) + fq;
        float xv = values[base0], mv = mask[base0], dv = deltas[base0];
        sx[bq][fq] = xv; smk[bq][fq] = mv; sd[bq][fq] = dv;
        sgx[bq][fq] = __expf(-fmaxf(dv * wdx_f + bdx_f, 0.f));
    }
    __syncthreads();

    float lx = 0.f, lm = 0.f;    // per-thread loss accumulators (A threads)

    for (int t = 0; t < Tq; t++) {
        // prefetch next-step inputs (registers; consumed at the bottom of the step)
        int tn = (t + 1 < Tq) ? t + 1 : t;
        int basen = (rowBase + bq)*(Tq*Fq) + tn*Fq + fq;
        float xv_n = values[basen], mv_n = mask[basen], dv_n = deltas[basen];

        ull a01[4], a23[4];
        #pragma unroll
        for (int b = 0; b < 4; b++) { a01[b] = 0ull; a23[b] = 0ull; }

        float al0, al1;   // A: alpha pre-activations, computed in W1, used in W2

        // ---- window 1 ----
        // B: full Wih-mask gemv.  A: stage 2 (float2 weights, MLP-32) + alpha gemvs.
        if (tid >= 256) {
            gemv_acc_h<Fq, Fq>(&g_WihT_h[Fq*1024 + j0], &smk[0][0], a01, a23);
        } else {
            // stage 2: gamma_h, decay h — 2 windows of 32 LDG.64 (64 k each)
            float a0 = 0.f, a1 = 0.f, a2 = 0.f, a3 = 0.f;
            #pragma unroll
            for (int kk = 0; kk < 2; kk++) {
                float2 w2[32];
                #pragma unroll
                for (int i = 0; i < 32; i++)
                    w2[i] = *(const float2*)&g_WdhT2[(kk*32 + i)*512 + tid*2];
                #pragma unroll
                for (int i = 0; i < 32; i++) {
                    int k = (kk*32 + i)*2;
                    a0 += w2[i].x * sd[0][k] + w2[i].y * sd[0][k+1];
                    a1 += w2[i].x * sd[1][k] + w2[i].y * sd[1][k+1];
                    a2 += w2[i].x * sd[2][k] + w2[i].y * sd[2][k+1];
                    a3 += w2[i].x * sd[3][k] + w2[i].y * sd[3][k+1];
                }
            }
            sh[0][tid] *= __expf(-fmaxf(a0 + bdh_j, 0.f));
            sh[1][tid] *= __expf(-fmaxf(a1 + bdh_j, 0.f));
            sh[2][tid] *= __expf(-fmaxf(a2 + bdh_j, 0.f));
            sh[3][tid] *= __expf(-fmaxf(a3 + bdh_j, 0.f));

            // stage-5 alpha gemvs: depend only on gamma_x and mask (ready since stage 1)
            {
                ull a  = gemv_pair_h(s_WcT, pA, &sgx[bA][0], Fq);
                ull a2q = gemv_pair_h(s_WcT + Fq*Fq, pA, &smk[bA][0], Fq);
                float s0, s1, q0, q1;
                unpack2(a, s0, s1); unpack2(a2q, q0, q1);
                al0 = s0 + q0 + bc2.x; al1 = s1 + q1 + bc2.y;
            }
        }
        __syncthreads();   // h now final until stage 7

        // ---- window 2 ----
        // B: Whh @ h -> sgate2.  A: stage 3 -> stage 4+combine -> Wih@c_c tail -> sgate.
        if (tid >= 256) {
            gemv_acc_h<Hq, Hq>(&g_WhhT_h[j0], &sh[0][0], a01, a23);
            #pragma unroll
            for (int b2 = 0; b2 < 4; b2++) {
                float g0, g1, g2, g3;
                unpack2(a01[b2], g0, g1);
                unpack2(a23[b2], g2, g3);
                float4 gv; gv.x = g0; gv.y = g1; gv.z = g2; gv.w = g3;
                *(float4*)&sgate2[b2][j0] = gv;
            }
        } else {
            const int p = pA, b = bA, f0 = f0A;
            float2 xp = *(const float2*)&sx[b][f0];
            float2 mp = *(const float2*)&smk[b][f0];

            // ---- stage 3: x_h = Wh @ h + bh; x_c; loss1 (fp16 SMEM) ----
            float xh0, xh1, l1;
            {
                ull a = gemv_pair_h(s_WhT, p, &sh[b][0], Hq);
                float s0, s1; unpack2(a, s0, s1);
                xh0 = s0 + bh2.x; xh1 = s1 + bh2.y;
                float2 xc;
                xc.x = mp.x*xp.x + (1.f - mp.x)*xh0;
                xc.y = mp.y*xp.y + (1.f - mp.y)*xh1;
                *(float2*)&sxc[b][f0] = xc;
                l1 = fabsf(xh0 - xp.x)*mp.x + fabsf(xh1 - xp.y)*mp.y;
            }
            asm volatile("bar.sync 1, 256;" ::: "memory");

            // ---- stage 4 + combine: z_h, then c_h/c_c with alpha from W1 ----
            {
                ull a = gemv_pair_h(s_WfT, p, &sxc[b][0], Fq);
                float s0, s1; unpack2(a, s0, s1);
                float zh0 = s0 + bf2.x, zh1 = s1 + bf2.y;
                float l2 = fabsf(zh0 - xp.x)*mp.x + fabsf(zh1 - xp.y)*mp.y;

                float ch0 = al0*zh0 + (1.f - al0)*xh0;
                float ch1 = al1*zh1 + (1.f - al1)*xh1;
                float l3 = fabsf(ch0 - xp.x)*mp.x + fabsf(ch1 - xp.y)*mp.y;
                float2 cc;
                cc.x = mp.x*xp.x + (1.f - mp.x)*ch0;
                cc.y = mp.y*xp.y + (1.f - mp.y)*ch1;
                *(float2*)&sccb[b][f0] = cc;
                *(float2*)&out[(rowBase + b)*(Tq*Fq) + t*Fq + f0] = cc;
                float inv = __fdividef(1.f, g_D[t] + 1e-9f);
                lx += (l1 + l2 + (float)(Tq - t)*l3) * inv;
                lm += l3 * inv;
            }
            asm volatile("bar.sync 1, 256;" ::: "memory");

            // ---- A tail: Wih @ c_c; sgate = cc-part + (bih + bhh) ----
            gemv_acc_h<Fq, Fq>(&g_WihT_h[j0], &sccb[0][0], a01, a23);
            #pragma unroll
            for (int b2 = 0; b2 < 4; b2++) {
                float g0, g1, g2, g3;
                unpack2(a01[b2], g0, g1);
                unpack2(a23[b2], g2, g3);
                float4 gv;
                gv.x = g0 + bsum4.x; gv.y = g1 + bsum4.y;
                gv.z = g2 + bsum4.z; gv.w = g3 + bsum4.w;
                *(float4*)&sgate[b2][j0] = gv;
            }
        }
        __syncthreads();

        // ---- phase E: stage 1(t+1) from prefetch + stage 7 (LSTM), one barrier ----
        {
            sx[bq][fq] = xv_n; smk[bq][fq] = mv_n; sd[bq][fq] = dv_n;
            sgx[bq][fq] = __expf(-fmaxf(dv_n * wdx_f + bdx_f, 0.f));

            int u = tid & 255;
            int bp = (tid >> 8) * 2;
            #pragma unroll
            for (int bb = 0; bb < 2; bb++) {
                int b = bp + bb;
                float ig = sgate[b][u]        + sgate2[b][u];
                float fg = sgate[b][Hq + u]   + sgate2[b][Hq + u];
                float gg = sgate[b][2*Hq + u] + sgate2[b][2*Hq + u];
                float og = sgate[b][3*Hq + u] + sgate2[b][3*Hq + u];
                float si = sigm(ig);
                float sf = sigm(fg);
                float so = sigm(og);
                float tg = __tanhf(gg);
                float cn = sf*sc[b][u] + si*tg;
                sc[b][u] = cn;
                sh[b][u] = so * __tanhf(cn);
            }
        }
        __syncthreads();
    }

    // ---- final loss reduction across the block ----
    for (int o = 16; o; o >>= 1) {
        lx += __shfl_down_sync(0xffffffffu, lx, o);
        lm += __shfl_down_sync(0xffffffffu, lm, o);
    }
    if (lane == 0) { redx[wid] = lx; redm[wid] = lm; }
    __syncthreads();
    if (tid == 0 && BTF + 1 < out_size) {
        float tx = 0.f, tm = 0.f;
        #pragma unroll
        for (int w = 0; w < 16; w++) { tx += redx[w]; tm += redm[w]; }
        atomicAdd(&out[BTF],     tx * (1.f / (Tq * 3.0f)));
        atomicAdd(&out[BTF + 1], tm * (1.f / (float)Tq));
    }
}

// ---------------- launch ----------------
extern "C" void kernel_launch(void* const* d_in, const int* in_sizes, int n_in,
                              void* d_out, int out_size)
{
    const float* values = (const float*)d_in[0];
    const float* mask   = (const float*)d_in[1];
    const float* deltas = (const float*)d_in[2];
    const float* Wdh    = (const float*)d_in[3];
    const float* bdh    = (const float*)d_in[4];
    const float* Wdx    = (const float*)d_in[5];
    const float* bdx    = (const float*)d_in[6];
    const float* Wh     = (const float*)d_in[7];
    const float* bh     = (const float*)d_in[8];
    const float* Wf     = (const float*)d_in[9];
    const float* bf_    = (const float*)d_in[10];
    const float* Wc     = (const float*)d_in[11];
    const float* bc     = (const float*)d_in[12];
    const float* Wih    = (const float*)d_in[13];
    const float* Whh    = (const float*)d_in[14];
    const float* bih    = (const float*)d_in[15];
    const float* bhh    = (const float*)d_in[16];
    float* out = (float*)d_out;

    cudaFuncSetAttribute(rits_persistent,
                         cudaFuncAttributeMaxDynamicSharedMemorySize, DYN_SMEM_BYTES);

    prep_weights<<<256, 256>>>(Wdh, Wh, Wf, Wc, Wih, Whh, Wdx, bih, bhh, out, out_size);
    mask_denom<<<Tq, 256>>>(mask);
    rits_persistent<<<Bq/4, 512, DYN_SMEM_BYTES>>>(values, mask, deltas, bdh, bdx,
                                                   bh, bf_, bc, out, out_size);
}